// round 1
// baseline (speedup 1.0000x reference)
#include <cuda_runtime.h>
#include <math.h>

#define N_NODES 50000
#define N_EDGES 800000
#define D0 1024
#define D1 512
#define D2 128
#define DOUT 14

// ---------------- scratch (device globals; no allocs allowed) ----------------
__device__ float g_deg[N_NODES];
__device__ float g_dis[N_NODES];
__device__ int   g_cnt[N_NODES];
__device__ int   g_rowptr[N_NODES + 1];
__device__ int   g_src[N_EDGES];
__device__ float g_wgt[N_EDGES];
__device__ float g_h1[(size_t)N_NODES * D1];   // X @ W1
__device__ float g_a1[(size_t)N_NODES * D1];   // relu(norm-agg + b1)
__device__ float g_h2[(size_t)N_NODES * D2];   // a1 @ W2
__device__ int   g_is64;

// ---------------- edge-index dtype detection (int64 vs int32) ----------------
// Values are < 50000, so for int64 data every high 32-bit word is 0.
__global__ void detect_idx_kernel(const void* eidx) {
    if (threadIdx.x == 0 && blockIdx.x == 0) {
        const int* p = (const int*)eidx;
        int ok64 = 1;
        for (int i = 1; i < 2048; i += 2) {
            if (p[i] != 0) { ok64 = 0; break; }
        }
        g_is64 = ok64;
    }
}

__device__ __forceinline__ int get_idx(const void* base, long i) {
    if (g_is64) return (int)((const long long*)base)[i];
    return ((const int*)base)[i];
}

// ---------------- degree / normalization / CSR build ----------------
__global__ void init_kernel() {
    int i = blockIdx.x * blockDim.x + threadIdx.x;
    if (i < N_NODES) { g_deg[i] = 1.0f; g_cnt[i] = 0; }
}

__global__ void edge_deg_kernel(const void* eidx, const float* __restrict__ ew) {
    int e = blockIdx.x * blockDim.x + threadIdx.x;
    if (e < N_EDGES) {
        int c = get_idx(eidx, (long)N_EDGES + e);  // col = targets
        atomicAdd(&g_deg[c], ew[e]);
        atomicAdd(&g_cnt[c], 1);
    }
}

__global__ void dis_kernel() {
    int i = blockIdx.x * blockDim.x + threadIdx.x;
    if (i < N_NODES) g_dis[i] = rsqrtf(g_deg[i]);  // deg >= 1 always
}

__global__ void scan_kernel() {
    __shared__ int part[1024];
    int tid = threadIdx.x;
    const int chunk = (N_NODES + 1023) / 1024;
    int start = tid * chunk;
    int end = start + chunk; if (end > N_NODES) end = N_NODES;
    int s = 0;
    for (int i = start; i < end; i++) s += g_cnt[i];
    part[tid] = s;
    __syncthreads();
    if (tid == 0) {
        int run = 0;
        for (int i = 0; i < 1024; i++) { int v = part[i]; part[i] = run; run += v; }
        g_rowptr[N_NODES] = run;
    }
    __syncthreads();
    int run = part[tid];
    for (int i = start; i < end; i++) {
        g_rowptr[i] = run;
        run += g_cnt[i];
        g_cnt[i] = 0;  // reset for scatter pass
    }
}

__global__ void scatter_kernel(const void* eidx, const float* __restrict__ ew) {
    int e = blockIdx.x * blockDim.x + threadIdx.x;
    if (e < N_EDGES) {
        int r = get_idx(eidx, e);
        int c = get_idx(eidx, (long)N_EDGES + e);
        int pos = g_rowptr[c] + atomicAdd(&g_cnt[c], 1);
        g_src[pos] = r;
        g_wgt[pos] = ew[e] * g_dis[r];  // pre-fold source normalization
    }
}

// ---------------- fp32 SGEMM: C[M,N] = A[M,K] @ B[K,N] ----------------
// 128x128 tile, BK=8, 256 threads, 8x8 per thread. N % 128 == 0, K % 8 == 0.
__global__ __launch_bounds__(256, 2)
void sgemm128(const float* __restrict__ A, const float* __restrict__ B,
              float* __restrict__ C, int M, int K, int N) {
    __shared__ float As[8][128];
    __shared__ float Bs[8][128];
    int tid = threadIdx.x;
    int ty = tid >> 4, tx = tid & 15;
    int rowBase = blockIdx.y * 128;
    int colBase = blockIdx.x * 128;

    int aRow = tid >> 1;             // 0..127
    int aCol4 = (tid & 1) * 4;       // 0 or 4
    int bRow = tid >> 5;             // 0..7
    int bCol = (tid & 31) * 4;       // 0..124

    bool aValid = (rowBase + aRow) < M;
    const float* Aptr = A + (size_t)(rowBase + aRow) * K + aCol4;
    const float* Bptr = B + (size_t)bRow * N + colBase + bCol;

    float acc[8][8];
#pragma unroll
    for (int i = 0; i < 8; i++)
#pragma unroll
        for (int j = 0; j < 8; j++) acc[i][j] = 0.f;

    for (int k0 = 0; k0 < K; k0 += 8) {
        float4 av = make_float4(0.f, 0.f, 0.f, 0.f);
        if (aValid) av = *(const float4*)(Aptr + k0);
        As[aCol4 + 0][aRow] = av.x;
        As[aCol4 + 1][aRow] = av.y;
        As[aCol4 + 2][aRow] = av.z;
        As[aCol4 + 3][aRow] = av.w;
        float4 bv = *(const float4*)(Bptr + (size_t)k0 * N);
        *(float4*)&Bs[bRow][bCol] = bv;
        __syncthreads();
#pragma unroll
        for (int k = 0; k < 8; k++) {
            float a[8], b[8];
            *(float4*)&a[0] = *(const float4*)&As[k][ty * 8];
            *(float4*)&a[4] = *(const float4*)&As[k][ty * 8 + 4];
            *(float4*)&b[0] = *(const float4*)&Bs[k][tx * 8];
            *(float4*)&b[4] = *(const float4*)&Bs[k][tx * 8 + 4];
#pragma unroll
            for (int i = 0; i < 8; i++)
#pragma unroll
                for (int j = 0; j < 8; j++)
                    acc[i][j] += a[i] * b[j];
        }
        __syncthreads();
    }

#pragma unroll
    for (int i = 0; i < 8; i++) {
        int m = rowBase + ty * 8 + i;
        if (m < M) {
            float4* cp = (float4*)(C + (size_t)m * N + colBase + tx * 8);
            cp[0] = make_float4(acc[i][0], acc[i][1], acc[i][2], acc[i][3]);
            cp[1] = make_float4(acc[i][4], acc[i][5], acc[i][6], acc[i][7]);
        }
    }
}

// ---------------- aggregation layer 1: 512 features, 1 warp / node ----------------
__global__ __launch_bounds__(256)
void agg1_kernel(const float* __restrict__ b1) {
    int node = blockIdx.x * 8 + (threadIdx.x >> 5);
    if (node >= N_NODES) return;
    int lane = threadIdx.x & 31;
    const float4* h = (const float4*)g_h1;  // 128 float4 per row
    float dc = g_dis[node];

    float4 acc[4];
#pragma unroll
    for (int i = 0; i < 4; i++) {
        float4 v = h[(size_t)node * 128 + lane + i * 32];
        acc[i] = make_float4(v.x * dc, v.y * dc, v.z * dc, v.w * dc);  // self loop
    }
    int beg = g_rowptr[node], end = g_rowptr[node + 1];
    for (int e = beg; e < end; e++) {
        int r = g_src[e];
        float w = g_wgt[e];
        const float4* hr = h + (size_t)r * 128;
#pragma unroll
        for (int i = 0; i < 4; i++) {
            float4 v = hr[lane + i * 32];
            acc[i].x += w * v.x; acc[i].y += w * v.y;
            acc[i].z += w * v.z; acc[i].w += w * v.w;
        }
    }
    float4* out = (float4*)g_a1;
    const float4* bb4 = (const float4*)b1;
#pragma unroll
    for (int i = 0; i < 4; i++) {
        float4 bb = bb4[lane + i * 32];
        float4 o;
        o.x = fmaxf(dc * acc[i].x + bb.x, 0.f);
        o.y = fmaxf(dc * acc[i].y + bb.y, 0.f);
        o.z = fmaxf(dc * acc[i].z + bb.z, 0.f);
        o.w = fmaxf(dc * acc[i].w + bb.w, 0.f);
        out[(size_t)node * 128 + lane + i * 32] = o;
    }
}

// ---------------- aggregation layer 2 (128 feats) fused with FC(128->14)+sigmoid ----------------
__global__ __launch_bounds__(256)
void agg2_fc_kernel(const float* __restrict__ b2, const float* __restrict__ Wfc,
                    const float* __restrict__ bfc, float* __restrict__ out) {
    __shared__ float sh[8][128];
    __shared__ float sWfc[D2 * DOUT];
    for (int i = threadIdx.x; i < D2 * DOUT; i += blockDim.x) sWfc[i] = Wfc[i];
    __syncthreads();

    int wid = threadIdx.x >> 5;
    int lane = threadIdx.x & 31;
    int node = blockIdx.x * 8 + wid;

    if (node < N_NODES) {
        const float4* h = (const float4*)g_h2;  // 32 float4 per row
        float dc = g_dis[node];
        float4 v = h[(size_t)node * 32 + lane];
        float4 acc = make_float4(v.x * dc, v.y * dc, v.z * dc, v.w * dc);
        int beg = g_rowptr[node], end = g_rowptr[node + 1];
        for (int e = beg; e < end; e++) {
            int r = g_src[e];
            float w = g_wgt[e];
            float4 u = h[(size_t)r * 32 + lane];
            acc.x += w * u.x; acc.y += w * u.y; acc.z += w * u.z; acc.w += w * u.w;
        }
        float4 bb = ((const float4*)b2)[lane];
        sh[wid][lane * 4 + 0] = fmaxf(dc * acc.x + bb.x, 0.f);
        sh[wid][lane * 4 + 1] = fmaxf(dc * acc.y + bb.y, 0.f);
        sh[wid][lane * 4 + 2] = fmaxf(dc * acc.z + bb.z, 0.f);
        sh[wid][lane * 4 + 3] = fmaxf(dc * acc.w + bb.w, 0.f);
    }
    __syncwarp();
    if (node < N_NODES && lane < DOUT) {
        float s = bfc[lane];
#pragma unroll 8
        for (int d = 0; d < D2; d++) s += sh[wid][d] * sWfc[d * DOUT + lane];
        out[(size_t)node * DOUT + lane] = 1.f / (1.f + expf(-s));
    }
}

// ---------------- launch ----------------
extern "C" void kernel_launch(void* const* d_in, const int* in_sizes, int n_in,
                              void* d_out, int out_size) {
    const float* x   = (const float*)d_in[0];
    const void*  eix = d_in[1];
    const float* ew  = (const float*)d_in[2];
    const float* W1  = (const float*)d_in[3];
    const float* b1  = (const float*)d_in[4];
    const float* W2  = (const float*)d_in[5];
    const float* b2  = (const float*)d_in[6];
    const float* Wfc = (const float*)d_in[7];
    const float* bfc = (const float*)d_in[8];
    float* out = (float*)d_out;

    float *h1p, *a1p, *h2p;
    cudaGetSymbolAddress((void**)&h1p, g_h1);
    cudaGetSymbolAddress((void**)&a1p, g_a1);
    cudaGetSymbolAddress((void**)&h2p, g_h2);

    const int TB = 256;
    detect_idx_kernel<<<1, 32>>>(eix);
    init_kernel<<<(N_NODES + TB - 1) / TB, TB>>>();
    edge_deg_kernel<<<(N_EDGES + TB - 1) / TB, TB>>>(eix, ew);
    dis_kernel<<<(N_NODES + TB - 1) / TB, TB>>>();
    scan_kernel<<<1, 1024>>>();
    scatter_kernel<<<(N_EDGES + TB - 1) / TB, TB>>>(eix, ew);

    dim3 g1(D1 / 128, (N_NODES + 127) / 128);
    sgemm128<<<g1, 256>>>(x, W1, h1p, N_NODES, D0, D1);

    agg1_kernel<<<(N_NODES + 7) / 8, 256>>>(b1);

    dim3 g2(D2 / 128, (N_NODES + 127) / 128);
    sgemm128<<<g2, 256>>>(a1p, W2, h2p, N_NODES, D1, D2);

    agg2_fc_kernel<<<(N_NODES + 7) / 8, 256>>>(b2, Wfc, bfc, out);
}

// round 2
// speedup vs baseline: 2.4170x; 2.4170x over previous
#include <cuda_runtime.h>
#include <math.h>

#define N_NODES 50000
#define N_EDGES 800000
#define D0 1024
#define D1 512
#define D2 128
#define DOUT 14

// ---------------- scratch (device globals; no allocs allowed) ----------------
__device__ float g_deg[N_NODES];
__device__ float g_dis[N_NODES];
__device__ int   g_cnt[N_NODES];
__device__ int   g_rowptr[N_NODES + 1];
__device__ int   g_src[N_EDGES];
__device__ float g_wgt[N_EDGES];
__device__ float g_h1[(size_t)N_NODES * D1];   // X @ W1
__device__ float g_a1[(size_t)N_NODES * D1];   // relu(norm-agg + b1)
__device__ float g_h2[(size_t)N_NODES * D2];   // a1 @ W2
__device__ int   g_is64;

// ---------------- edge-index dtype detection (int64 vs int32) ----------------
__global__ void detect_idx_kernel(const void* eidx) {
    if (threadIdx.x == 0 && blockIdx.x == 0) {
        const int* p = (const int*)eidx;
        int ok64 = 1;
        for (int i = 1; i < 2048; i += 2) {
            if (p[i] != 0) { ok64 = 0; break; }
        }
        g_is64 = ok64;
    }
}

__device__ __forceinline__ int get_idx(const void* base, long i) {
    if (g_is64) return (int)((const long long*)base)[i];
    return ((const int*)base)[i];
}

// ---------------- degree / normalization / CSR build ----------------
__global__ void init_kernel() {
    int i = blockIdx.x * blockDim.x + threadIdx.x;
    if (i < N_NODES) { g_deg[i] = 1.0f; g_cnt[i] = 0; }
}

__global__ void edge_deg_kernel(const void* eidx, const float* __restrict__ ew) {
    int e = blockIdx.x * blockDim.x + threadIdx.x;
    if (e < N_EDGES) {
        int c = get_idx(eidx, (long)N_EDGES + e);
        atomicAdd(&g_deg[c], ew[e]);
        atomicAdd(&g_cnt[c], 1);
    }
}

__global__ void dis_kernel() {
    int i = blockIdx.x * blockDim.x + threadIdx.x;
    if (i < N_NODES) g_dis[i] = rsqrtf(g_deg[i]);
}

__global__ void scan_kernel() {
    __shared__ int part[1024];
    int tid = threadIdx.x;
    const int chunk = (N_NODES + 1023) / 1024;
    int start = tid * chunk;
    int end = start + chunk; if (end > N_NODES) end = N_NODES;
    int s = 0;
    for (int i = start; i < end; i++) s += g_cnt[i];
    part[tid] = s;
    __syncthreads();
    if (tid == 0) {
        int run = 0;
        for (int i = 0; i < 1024; i++) { int v = part[i]; part[i] = run; run += v; }
        g_rowptr[N_NODES] = run;
    }
    __syncthreads();
    int run = part[tid];
    for (int i = start; i < end; i++) {
        g_rowptr[i] = run;
        run += g_cnt[i];
        g_cnt[i] = 0;
    }
}

__global__ void scatter_kernel(const void* eidx, const float* __restrict__ ew) {
    int e = blockIdx.x * blockDim.x + threadIdx.x;
    if (e < N_EDGES) {
        int r = get_idx(eidx, e);
        int c = get_idx(eidx, (long)N_EDGES + e);
        int pos = g_rowptr[c] + atomicAdd(&g_cnt[c], 1);
        g_src[pos] = r;
        g_wgt[pos] = ew[e] * g_dis[r];
    }
}

// ---------------- tf32 tensor-core GEMM: C[M,N] = A[M,K] @ B[K,N] ----------------
// BM=128, BN=128, BK=32; 256 threads = 8 warps (4x2); warp tile 32x64.
// mma.sync.aligned.m16n8k8.row.col.f32.tf32.tf32.f32, fp32 accumulate.
// Requires N % 128 == 0, K % 32 == 0. M guarded.
#define BM 128
#define BN 128
#define BK 32

__device__ __forceinline__ float to_tf32(float x) {
    float r;
    asm("cvt.rna.tf32.f32 %0, %1;" : "=f"(r) : "f"(x));
    return r;
}

__device__ __forceinline__ void mma_tf32(float* d, const float* a, const float* b) {
    asm volatile(
        "mma.sync.aligned.m16n8k8.row.col.f32.tf32.tf32.f32 "
        "{%0,%1,%2,%3}, {%4,%5,%6,%7}, {%8,%9}, {%0,%1,%2,%3};"
        : "+f"(d[0]), "+f"(d[1]), "+f"(d[2]), "+f"(d[3])
        : "f"(a[0]), "f"(a[1]), "f"(a[2]), "f"(a[3]),
          "f"(b[0]), "f"(b[1]));
}

__global__ __launch_bounds__(256, 2)
void tf32gemm(const float* __restrict__ A, const float* __restrict__ B,
              float* __restrict__ C, int M, int K, int N) {
    __shared__ float As[BM][BK + 4];   // stride 36: frag banks (4g+t)%32 bijective
    __shared__ float Bs[BK][BN + 8];   // stride 136: frag banks (8t+g)%32 bijective

    int tid = threadIdx.x;
    int warp = tid >> 5, lane = tid & 31;
    int g = lane >> 2, t = lane & 3;
    int wm = (warp >> 1) * 32;   // warp m offset: 0,32,64,96
    int wn = (warp & 1) * 64;    // warp n offset: 0,64

    int rowBase = blockIdx.y * BM;
    int colBase = blockIdx.x * BN;

    // gmem load mapping
    int lm  = tid >> 3;          // 0..31 (A row within pass)
    int lk4 = (tid & 7) * 4;     // 0,4,...,28
    int bk  = tid >> 5;          // 0..7 (B row within pass)
    int bn4 = lane * 4;          // 0..124

    float acc[2][8][4];
#pragma unroll
    for (int mi = 0; mi < 2; mi++)
#pragma unroll
        for (int ni = 0; ni < 8; ni++)
#pragma unroll
            for (int r = 0; r < 4; r++) acc[mi][ni][r] = 0.f;

    for (int k0 = 0; k0 < K; k0 += BK) {
        // load A tile: 4 passes x 32 rows, convert to tf32 at store
#pragma unroll
        for (int p = 0; p < 4; p++) {
            int m = p * 32 + lm;
            float4 v = make_float4(0.f, 0.f, 0.f, 0.f);
            if (rowBase + m < M)
                v = *(const float4*)(A + (size_t)(rowBase + m) * K + k0 + lk4);
            float4 w = make_float4(to_tf32(v.x), to_tf32(v.y), to_tf32(v.z), to_tf32(v.w));
            *(float4*)&As[m][lk4] = w;
        }
        // load B tile: 4 passes x 8 rows
#pragma unroll
        for (int p = 0; p < 4; p++) {
            int kk = p * 8 + bk;
            float4 v = *(const float4*)(B + (size_t)(k0 + kk) * N + colBase + bn4);
            float4 w = make_float4(to_tf32(v.x), to_tf32(v.y), to_tf32(v.z), to_tf32(v.w));
            *(float4*)&Bs[kk][bn4] = w;
        }
        __syncthreads();

#pragma unroll
        for (int kk = 0; kk < BK; kk += 8) {
            float a[2][4];
#pragma unroll
            for (int mi = 0; mi < 2; mi++) {
                int row = wm + mi * 16;
                a[mi][0] = As[row + g    ][kk + t    ];
                a[mi][1] = As[row + g + 8][kk + t    ];
                a[mi][2] = As[row + g    ][kk + t + 4];
                a[mi][3] = As[row + g + 8][kk + t + 4];
            }
            float b[8][2];
#pragma unroll
            for (int ni = 0; ni < 8; ni++) {
                int col = wn + ni * 8;
                b[ni][0] = Bs[kk + t    ][col + g];
                b[ni][1] = Bs[kk + t + 4][col + g];
            }
#pragma unroll
            for (int mi = 0; mi < 2; mi++)
#pragma unroll
                for (int ni = 0; ni < 8; ni++)
                    mma_tf32(acc[mi][ni], a[mi], b[ni]);
        }
        __syncthreads();
    }

    // epilogue: c0/c1 at (row, 2t), c2/c3 at (row+8, 2t)
#pragma unroll
    for (int mi = 0; mi < 2; mi++) {
        int row0 = rowBase + wm + mi * 16 + g;
        int row1 = row0 + 8;
#pragma unroll
        for (int ni = 0; ni < 8; ni++) {
            int col = colBase + wn + ni * 8 + t * 2;
            if (row0 < M) {
                C[(size_t)row0 * N + col    ] = acc[mi][ni][0];
                C[(size_t)row0 * N + col + 1] = acc[mi][ni][1];
            }
            if (row1 < M) {
                C[(size_t)row1 * N + col    ] = acc[mi][ni][2];
                C[(size_t)row1 * N + col + 1] = acc[mi][ni][3];
            }
        }
    }
}

// ---------------- aggregation layer 1: 512 features, 1 warp / node ----------------
__global__ __launch_bounds__(256)
void agg1_kernel(const float* __restrict__ b1) {
    int node = blockIdx.x * 8 + (threadIdx.x >> 5);
    if (node >= N_NODES) return;
    int lane = threadIdx.x & 31;
    const float4* h = (const float4*)g_h1;
    float dc = g_dis[node];

    float4 acc[4];
#pragma unroll
    for (int i = 0; i < 4; i++) {
        float4 v = h[(size_t)node * 128 + lane + i * 32];
        acc[i] = make_float4(v.x * dc, v.y * dc, v.z * dc, v.w * dc);
    }
    int beg = g_rowptr[node], end = g_rowptr[node + 1];
    for (int e = beg; e < end; e++) {
        int r = g_src[e];
        float w = g_wgt[e];
        const float4* hr = h + (size_t)r * 128;
#pragma unroll
        for (int i = 0; i < 4; i++) {
            float4 v = hr[lane + i * 32];
            acc[i].x += w * v.x; acc[i].y += w * v.y;
            acc[i].z += w * v.z; acc[i].w += w * v.w;
        }
    }
    float4* out = (float4*)g_a1;
    const float4* bb4 = (const float4*)b1;
#pragma unroll
    for (int i = 0; i < 4; i++) {
        float4 bb = bb4[lane + i * 32];
        float4 o;
        o.x = fmaxf(dc * acc[i].x + bb.x, 0.f);
        o.y = fmaxf(dc * acc[i].y + bb.y, 0.f);
        o.z = fmaxf(dc * acc[i].z + bb.z, 0.f);
        o.w = fmaxf(dc * acc[i].w + bb.w, 0.f);
        out[(size_t)node * 128 + lane + i * 32] = o;
    }
}

// ---------------- aggregation layer 2 fused with FC(128->14)+sigmoid ----------------
__global__ __launch_bounds__(256)
void agg2_fc_kernel(const float* __restrict__ b2, const float* __restrict__ Wfc,
                    const float* __restrict__ bfc, float* __restrict__ out) {
    __shared__ float sh[8][128];
    __shared__ float sWfc[D2 * DOUT];
    for (int i = threadIdx.x; i < D2 * DOUT; i += blockDim.x) sWfc[i] = Wfc[i];
    __syncthreads();

    int wid = threadIdx.x >> 5;
    int lane = threadIdx.x & 31;
    int node = blockIdx.x * 8 + wid;

    if (node < N_NODES) {
        const float4* h = (const float4*)g_h2;
        float dc = g_dis[node];
        float4 v = h[(size_t)node * 32 + lane];
        float4 acc = make_float4(v.x * dc, v.y * dc, v.z * dc, v.w * dc);
        int beg = g_rowptr[node], end = g_rowptr[node + 1];
        for (int e = beg; e < end; e++) {
            int r = g_src[e];
            float w = g_wgt[e];
            float4 u = h[(size_t)r * 32 + lane];
            acc.x += w * u.x; acc.y += w * u.y; acc.z += w * u.z; acc.w += w * u.w;
        }
        float4 bb = ((const float4*)b2)[lane];
        sh[wid][lane * 4 + 0] = fmaxf(dc * acc.x + bb.x, 0.f);
        sh[wid][lane * 4 + 1] = fmaxf(dc * acc.y + bb.y, 0.f);
        sh[wid][lane * 4 + 2] = fmaxf(dc * acc.z + bb.z, 0.f);
        sh[wid][lane * 4 + 3] = fmaxf(dc * acc.w + bb.w, 0.f);
    }
    __syncwarp();
    if (node < N_NODES && lane < DOUT) {
        float s = bfc[lane];
#pragma unroll 8
        for (int d = 0; d < D2; d++) s += sh[wid][d] * sWfc[d * DOUT + lane];
        out[(size_t)node * DOUT + lane] = 1.f / (1.f + expf(-s));
    }
}

// ---------------- launch ----------------
extern "C" void kernel_launch(void* const* d_in, const int* in_sizes, int n_in,
                              void* d_out, int out_size) {
    const float* x   = (const float*)d_in[0];
    const void*  eix = d_in[1];
    const float* ew  = (const float*)d_in[2];
    const float* W1  = (const float*)d_in[3];
    const float* b1  = (const float*)d_in[4];
    const float* W2  = (const float*)d_in[5];
    const float* b2  = (const float*)d_in[6];
    const float* Wfc = (const float*)d_in[7];
    const float* bfc = (const float*)d_in[8];
    float* out = (float*)d_out;

    float *h1p, *a1p, *h2p;
    cudaGetSymbolAddress((void**)&h1p, g_h1);
    cudaGetSymbolAddress((void**)&a1p, g_a1);
    cudaGetSymbolAddress((void**)&h2p, g_h2);

    const int TB = 256;
    detect_idx_kernel<<<1, 32>>>(eix);
    init_kernel<<<(N_NODES + TB - 1) / TB, TB>>>();
    edge_deg_kernel<<<(N_EDGES + TB - 1) / TB, TB>>>(eix, ew);
    dis_kernel<<<(N_NODES + TB - 1) / TB, TB>>>();
    scan_kernel<<<1, 1024>>>();
    scatter_kernel<<<(N_EDGES + TB - 1) / TB, TB>>>(eix, ew);

    dim3 g1(D1 / BN, (N_NODES + BM - 1) / BM);
    tf32gemm<<<g1, 256>>>(x, W1, h1p, N_NODES, D0, D1);

    agg1_kernel<<<(N_NODES + 7) / 8, 256>>>(b1);

    dim3 g2(D2 / BN, (N_NODES + BM - 1) / BM);
    tf32gemm<<<g2, 256>>>(a1p, W2, h2p, N_NODES, D1, D2);

    agg2_fc_kernel<<<(N_NODES + 7) / 8, 256>>>(b2, Wfc, bfc, out);
}